// round 13
// baseline (speedup 1.0000x reference)
#include <cuda_runtime.h>
#include <cuda_fp16.h>
#include <cstdint>

// ---------------- problem constants ----------------
#define BATCH 4096
#define FST   20
#define FDY   10
#define MLEN  50
#define EDIM  16
#define FALL  30
#define PAIRS 435
#define DIN   6960          // PAIRS * EDIM
#define KPAD1 7040          // DIN padded to 64*110 (split-K 2 x 55)
#define HID   512
#define BN_EPS 1e-5f
#define XSCALE 64.0f        // fp16 subnormal guard: x stored as 64*x, W1 folded /64

// ---------------- device scratch (static, no allocation) ----------------
__device__ __align__(256) __half d_x[(size_t)BATCH * KPAD1];       // 64*x, fp16
__device__ float d_lr[BATCH];

__device__ float d_ps1[16 * DIN], d_pq1[16 * DIN];
__device__ float d_sc1[DIN], d_t1[DIN];
__device__ __align__(256) __half d_w1t[(size_t)HID * KPAD1];       // sc1*W1/64, [N][K]
__device__ float d_bp1[220 * HID];
__device__ float d_b1p[HID];
__device__ __align__(256) __half d_h1[(size_t)BATCH * HID];

__device__ __align__(256) float d_cpar[2 * (size_t)BATCH * HID];   // split-K partials
__device__ int d_tilecnt[128];                                      // self-resetting

__device__ float d_ps2[16 * HID], d_pq2[16 * HID];
__device__ float d_sc2[HID], d_t2[HID];
__device__ __align__(256) __half d_w2t[(size_t)HID * HID];
__device__ float d_bp2[16 * HID];
__device__ float d_b2p[HID];
__device__ __align__(256) float d_h2[(size_t)BATCH * HID];

__device__ float d_ps3[16 * HID], d_pq3[16 * HID];
__device__ float d_sc3[HID], d_t3[HID];
__device__ float d_coeff[HID], d_cpart[HID];

// ---------------- portable PTX helpers ----------------
__device__ __forceinline__ uint32_t smem_u32(const void* p) {
    uint32_t a;
    asm("{ .reg .u64 t; cvta.to.shared.u64 t, %1; cvt.u32.u64 %0, t; }" : "=r"(a) : "l"(p));
    return a;
}
#define CP16(s, g)  asm volatile("cp.async.cg.shared.global [%0], [%1], 16;" :: "r"(s), "l"(g) : "memory")
#define CP_COMMIT() asm volatile("cp.async.commit_group;" ::: "memory")

__device__ __forceinline__ void hmma16816(float* c, const uint32_t* a, const uint32_t* b) {
    asm volatile(
        "mma.sync.aligned.m16n8k16.row.col.f32.f16.f16.f32 "
        "{%0,%1,%2,%3}, {%4,%5,%6,%7}, {%8,%9}, {%0,%1,%2,%3};"
        : "+f"(c[0]), "+f"(c[1]), "+f"(c[2]), "+f"(c[3])
        : "r"(a[0]), "r"(a[1]), "r"(a[2]), "r"(a[3]), "r"(b[0]), "r"(b[1]));
}

// ---------------- K1: gather + dyn-mean + lr + pair products -------------
__global__ void k_gather(const int* __restrict__ st_ids, const int* __restrict__ dy_ids,
                         const int* __restrict__ dy_len,
                         const float* __restrict__ st_emb, const float* __restrict__ dy_emb,
                         const float* __restrict__ st_lr, const float* __restrict__ dy_lr,
                         __half* __restrict__ xout, float* __restrict__ lr_out) {
    __shared__ float semb[FALL * EDIM];
    __shared__ float slr[FALL];
    int b = blockIdx.x, t = threadIdx.x;

    // pair index for this thread (kept in registers; used in phase 2)
    int ir = 0, jr = 0;
    if (t < PAIRS) {
        int p = t, i = 0, rem = FALL - 1;
        while (p >= rem) { p -= rem; i++; rem--; }
        ir = i;
        jr = i + 1 + p;
    }
    if (t < FST * EDIM) {                       // static fields (warps 0-9)
        int f = t >> 4, e = t & 15;
        int id = st_ids[b * FST + f];
        semb[t] = st_emb[id * EDIM + e];
        if (e == 0) slr[f] = st_lr[id];
    } else if (t < FALL * EDIM + FDY * EDIM) {  // dynamic: 2 lanes per (f,e)
        int u = t - FST * EDIM;                 // 0..319, one warp per field
        int f = u >> 5;
        int v = u & 31;
        int e = v & 15, half = v >> 4;
        int len = dy_len[b * FDY + f];
        if (len < 1) len = 1;
        const int* ids = dy_ids + ((size_t)b * FDY + f) * MLEN;
        float acc = 0.f, lacc = 0.f;
        #pragma unroll 4
        for (int m = half; m < len; m += 2) {
            int id = ids[m];
            acc += dy_emb[(size_t)id * EDIM + e];
            if (e == 0) lacc += dy_lr[id];
        }
        float acc2  = acc  + __shfl_xor_sync(0xFFFFFFFFu, acc, 16);
        float lacc2 = lacc + __shfl_xor_sync(0xFFFFFFFFu, lacc, 16);
        if (v < 16) {
            semb[(FST + f) * EDIM + e] = acc2 / (float)len;
            if (e == 0) slr[FST + f] = lacc2;
        }
    }
    __syncthreads();

    // phase 2: one pair per thread, vectorized 2x16B stores
    __half* xr = xout + (size_t)b * KPAD1;
    if (t < PAIRS) {
        const float4* ra = reinterpret_cast<const float4*>(semb + ir * EDIM);
        const float4* rb = reinterpret_cast<const float4*>(semb + jr * EDIM);
        uint4 outw[2];
        __half2* oh = reinterpret_cast<__half2*>(outw);
        #pragma unroll
        for (int q = 0; q < 4; q++) {
            float4 a4 = ra[q], b4 = rb[q];
            oh[2 * q + 0] = __floats2half2_rn(a4.x * b4.x * XSCALE, a4.y * b4.y * XSCALE);
            oh[2 * q + 1] = __floats2half2_rn(a4.z * b4.z * XSCALE, a4.w * b4.w * XSCALE);
        }
        *(uint4*)(xr + t * 16)     = outw[0];
        *(uint4*)(xr + t * 16 + 8) = outw[1];
    } else if (t < PAIRS + 5) {                 // zero pad region [DIN, KPAD1)
        uint4 z = {0u, 0u, 0u, 0u};
        *(uint4*)(xr + DIN + (t - PAIRS) * 16)     = z;
        *(uint4*)(xr + DIN + (t - PAIRS) * 16 + 8) = z;
    }
    if (t == 0) {
        float s = 0.f;
        #pragma unroll
        for (int f = 0; f < FALL; f++) s += slr[f];
        lr_out[b] = s;
    }
}

// ---------------- column stats over an fp16 plane (scaled) ---------------
__global__ void k_colstat_part_h(const __half* __restrict__ X,
                                 float* __restrict__ psum, float* __restrict__ psq,
                                 int ncol, int pitch, float scale) {
    int c = blockIdx.x * blockDim.x + threadIdx.x;
    if (c >= ncol) return;
    const int ROWS = BATCH / 16;
    size_t base = (size_t)blockIdx.y * ROWS * pitch + c;
    float s = 0.f, q = 0.f;
    for (int r = 0; r < ROWS; r++) {
        float v = __half2float(X[base + (size_t)r * pitch]) * scale;
        s += v; q += v * v;
    }
    psum[blockIdx.y * ncol + c] = s;
    psq[blockIdx.y * ncol + c] = q;
}

// fp32 variant (for h2)
__global__ void k_colstat_part(const float* __restrict__ X, float* __restrict__ psum,
                               float* __restrict__ psq, int ncol) {
    int c = blockIdx.x * blockDim.x + threadIdx.x;
    if (c >= ncol) return;
    const int ROWS = BATCH / 16;
    const float* p = X + (size_t)blockIdx.y * ROWS * ncol + c;
    float s = 0.f, q = 0.f;
    for (int r = 0; r < ROWS; r++) {
        float v = p[(size_t)r * ncol];
        s += v; q += v * v;
    }
    psum[blockIdx.y * ncol + c] = s;
    psq[blockIdx.y * ncol + c] = q;
}

__global__ void k_colstat_final(const float* __restrict__ psum, const float* __restrict__ psq,
                                const float* __restrict__ g, const float* __restrict__ bb,
                                float* __restrict__ sc, float* __restrict__ tsh, int ncol) {
    int c = blockIdx.x * blockDim.x + threadIdx.x;
    if (c >= ncol) return;
    float s = 0.f, q = 0.f;
    #pragma unroll
    for (int p = 0; p < 16; p++) { s += psum[p * ncol + c]; q += psq[p * ncol + c]; }
    float m = s * (1.f / BATCH);
    float v = q * (1.f / BATCH) - m * m;
    float scale = g[c] * rsqrtf(v + BN_EPS);
    sc[c]  = scale;
    tsh[c] = bb[c] - scale * m;
}

// ---------------- transpose + BN-scale + fp16 + bias partials ------------
__global__ void k_transpose_split(const float* __restrict__ W, const float* __restrict__ sc,
                                  const float* __restrict__ tsh, int Kdim, int Kpad,
                                  float wscale, __half* __restrict__ Wt,
                                  float* __restrict__ bpart) {
    __shared__ float tile[32][33];
    __shared__ float bred[8][32];
    int d0 = blockIdx.x * 32, h0 = blockIdx.y * 32;
    int tx = threadIdx.x, ty0 = threadIdx.y;
    float bacc = 0.f;
    for (int yy = ty0; yy < 32; yy += 8) {
        int d = d0 + yy;
        float w = 0.f, scl = 0.f, ts = 0.f;
        if (d < Kdim) {
            w = W[(size_t)d * HID + h0 + tx];
            scl = sc[d]; ts = tsh[d];
        }
        tile[yy][tx] = w * scl * wscale;
        bacc += ts * w;
    }
    bred[ty0][tx] = bacc;
    __syncthreads();
    for (int yy = ty0; yy < 32; yy += 8) {
        int h = h0 + yy, d = d0 + tx;
        Wt[(size_t)h * Kpad + d] = __float2half(tile[tx][yy]);
    }
    if (ty0 == 0) {
        float s = 0.f;
        #pragma unroll
        for (int r = 0; r < 8; r++) s += bred[r][tx];
        bpart[(size_t)blockIdx.x * HID + h0 + tx] = s;
    }
}

__global__ void k_bias_final(const float* __restrict__ blin, const float* __restrict__ bpart,
                             float* __restrict__ bout, int nparts) {
    int h = threadIdx.x;
    float a = blin[h];
    for (int p = 0; p < nparts; p++) a += bpart[p * HID + h];
    bout[h] = a;
}

// ---------------- mma.sync fp16 GEMM, split-K x2, fused last-CTA epilogue
// C[M, N=512] = relu(A[M,K] @ B^T + bias)  (B stored [N][K] K-major, fp16)
// 128x128 CTA tile, BK=64, 256 threads; warp tile 32x64 (2 m16 x 8 n8).
// Both z-CTAs write fp32 partials; the later one (atomic tile counter)
// combines other's partial + own registers, applies bias+ReLU, writes out.
// fp add is commutative -> bit-deterministic. Counter self-resets to 0.
#define BK      64
#define ROWB    144         // smem row stride bytes (128B data + 16B pad)
#define TILE_B  18432       // 128 rows * 144 B
#define STAGE_B 36864       // 2 tiles (A, B)
#define SMEM_MMA_BYTES (2 * STAGE_B)

__device__ __forceinline__ void ld_chunk(uint32_t sb, int st,
        const __half* A, const __half* B,
        int row0, int col0, int Kpad, int k0, int tid) {
    const __half* tp[2] = {A, B};
    #pragma unroll
    for (int tile = 0; tile < 2; tile++) {
        int rbase = tile ? col0 : row0;
        #pragma unroll
        for (int h = 0; h < 4; h++) {
            int ch  = tid + h * 256;          // 0..1023 (128 rows x 8 16B-chunks)
            int row = ch >> 3, c16 = ch & 7;
            uint32_t sa = sb + st * STAGE_B + tile * TILE_B + row * ROWB + c16 * 16;
            const __half* g = tp[tile] + (size_t)(rbase + row) * Kpad + k0 + c16 * 8;
            CP16(sa, g);
        }
    }
    CP_COMMIT();
}

__global__ __launch_bounds__(256, 2)
void k_mma(const __half* __restrict__ A, const __half* __restrict__ B,
           float* __restrict__ Cpart, const float* __restrict__ bias,
           __half* __restrict__ OutH, float* __restrict__ OutF32,
           int* __restrict__ tilecnt, int Kpad, int NC) {
    extern __shared__ __align__(16) char smem[];
    uint32_t sb = smem_u32(smem);
    int tid = threadIdx.x, wid = tid >> 5, lane = tid & 31;
    int row0 = blockIdx.y * 128, col0 = blockIdx.x * 128;
    int k0 = blockIdx.z * NC * BK;
    float* Cp = Cpart + (size_t)blockIdx.z * BATCH * HID;
    int wr = (wid & 3) * 32;
    int wc = (wid >> 2) * 64;
    int tq = lane >> 2;
    int tr = (lane & 3) * 2;

    float acc[2][8][4];
    #pragma unroll
    for (int i = 0; i < 2; i++)
        #pragma unroll
        for (int j = 0; j < 8; j++)
            #pragma unroll
            for (int q = 0; q < 4; q++) acc[i][j][q] = 0.f;

    ld_chunk(sb, 0, A, B, row0, col0, Kpad, k0, tid);
    ld_chunk(sb, 1, A, B, row0, col0, Kpad, k0 + BK, tid);

    for (int c = 0; c < NC; c++) {
        if (c + 1 < NC) asm volatile("cp.async.wait_group 1;" ::: "memory");
        else            asm volatile("cp.async.wait_group 0;" ::: "memory");
        __syncthreads();

        const char* st = smem + (c & 1) * STAGE_B;
        const char* As = st;
        const char* Bs = st + TILE_B;

        #pragma unroll
        for (int ks = 0; ks < 4; ks++) {
            int kk = ks * 16;
            uint32_t af[2][4], bf[8][2];
            #pragma unroll
            for (int mt = 0; mt < 2; mt++) {
                int mA = wr + mt * 16 + tq;
                af[mt][0] = *(const uint32_t*)(As + mA * ROWB + (kk + tr) * 2);
                af[mt][1] = *(const uint32_t*)(As + (mA + 8) * ROWB + (kk + tr) * 2);
                af[mt][2] = *(const uint32_t*)(As + mA * ROWB + (kk + 8 + tr) * 2);
                af[mt][3] = *(const uint32_t*)(As + (mA + 8) * ROWB + (kk + 8 + tr) * 2);
            }
            #pragma unroll
            for (int nt = 0; nt < 8; nt++) {
                int nB = wc + nt * 8 + tq;
                bf[nt][0] = *(const uint32_t*)(Bs + nB * ROWB + (kk + tr) * 2);
                bf[nt][1] = *(const uint32_t*)(Bs + nB * ROWB + (kk + 8 + tr) * 2);
            }
            #pragma unroll
            for (int mt = 0; mt < 2; mt++)
                #pragma unroll
                for (int nt = 0; nt < 8; nt++) hmma16816(acc[mt][nt], af[mt], bf[nt]);
        }
        __syncthreads();
        if (c + 2 < NC)
            ld_chunk(sb, c & 1, A, B, row0, col0, Kpad, k0 + (c + 2) * BK, tid);
    }

    // write own fp32 partial
    #pragma unroll
    for (int mt = 0; mt < 2; mt++) {
        #pragma unroll
        for (int nt = 0; nt < 8; nt++) {
            int m = row0 + wr + mt * 16 + tq;
            int n = col0 + wc + nt * 8 + tr;
            *(float2*)(Cp + (size_t)m * HID + n)       = make_float2(acc[mt][nt][0], acc[mt][nt][1]);
            *(float2*)(Cp + (size_t)(m + 8) * HID + n) = make_float2(acc[mt][nt][2], acc[mt][nt][3]);
        }
    }
    __threadfence();
    __shared__ int s_old;
    __syncthreads();
    int tile = blockIdx.y * 4 + blockIdx.x;
    if (tid == 0) s_old = atomicAdd(&tilecnt[tile], 1);
    __syncthreads();
    if (s_old != 1) return;         // first CTA of the pair: done

    // last CTA: combine other partial + own regs, bias + ReLU, write output
    __threadfence();
    const float* Co = Cpart + (size_t)(1 - blockIdx.z) * BATCH * HID;
    #pragma unroll
    for (int mt = 0; mt < 2; mt++) {
        #pragma unroll
        for (int nt = 0; nt < 8; nt++) {
            int m = row0 + wr + mt * 16 + tq;
            int n = col0 + wc + nt * 8 + tr;
            float b0 = bias[n], b1 = bias[n + 1];
            float2 o0 = *(const float2*)(Co + (size_t)m * HID + n);
            float2 o1 = *(const float2*)(Co + (size_t)(m + 8) * HID + n);
            float v00 = fmaxf(acc[mt][nt][0] + o0.x + b0, 0.f);
            float v01 = fmaxf(acc[mt][nt][1] + o0.y + b1, 0.f);
            float v10 = fmaxf(acc[mt][nt][2] + o1.x + b0, 0.f);
            float v11 = fmaxf(acc[mt][nt][3] + o1.y + b1, 0.f);
            if (OutF32) {
                *(float2*)(OutF32 + (size_t)m * HID + n)       = make_float2(v00, v01);
                *(float2*)(OutF32 + (size_t)(m + 8) * HID + n) = make_float2(v10, v11);
            } else {
                __half2 p0 = __floats2half2_rn(v00, v01);
                __half2 p1 = __floats2half2_rn(v10, v11);
                *(__half2*)(OutH + (size_t)m * HID + n)       = p0;
                *(__half2*)(OutH + (size_t)(m + 8) * HID + n) = p1;
            }
        }
    }
    if (tid == 0) tilecnt[tile] = 0;   // self-reset for next launch/replay
}

// ---------------- GEMM3 collapsed: coeff[k] = sc3[k]*rowsum(W3[k,:]) -----
__global__ void k_coeff(const float* __restrict__ W3, const float* __restrict__ sc3,
                        const float* __restrict__ t3, float* __restrict__ coeff,
                        float* __restrict__ cpart) {
    int k = blockIdx.x, t = threadIdx.x;
    float a = 0.f;
    for (int j = t; j < HID; j += 128) a += W3[(size_t)k * HID + j];
    __shared__ float r[128];
    r[t] = a; __syncthreads();
    for (int s = 64; s > 0; s >>= 1) { if (t < s) r[t] += r[t + s]; __syncthreads(); }
    if (t == 0) {
        float w = r[0];
        coeff[k] = sc3[k] * w;
        cpart[k] = t3[k] * w;
    }
}

// ---------------- final scores ----------------
__global__ void k_scores(const float* __restrict__ h2r, const float* __restrict__ lr,
                         const float* __restrict__ coeff, const float* __restrict__ cpart,
                         const float* __restrict__ b3, const float* __restrict__ biasp,
                         float* __restrict__ out) {
    __shared__ float sco[HID];
    __shared__ float red[256];
    int t = threadIdx.x;
    sco[t] = coeff[t]; sco[t + 256] = coeff[t + 256];
    float c = cpart[t] + b3[t] + cpart[t + 256] + b3[t + 256];
    red[t] = c; __syncthreads();
    for (int s = 128; s > 0; s >>= 1) { if (t < s) red[t] += red[t + s]; __syncthreads(); }

    int warp = t >> 5, lane = t & 31;
    int row = blockIdx.x * 8 + warp;
    const float* hr = h2r + (size_t)row * HID;
    float acc = 0.f;
    #pragma unroll
    for (int k = lane; k < HID; k += 32) acc += sco[k] * hr[k];
    #pragma unroll
    for (int o = 16; o > 0; o >>= 1) acc += __shfl_xor_sync(0xFFFFFFFFu, acc, o);
    if (lane == 0) out[row] = biasp[0] + lr[row] + acc + red[0];
}

// ---------------- launcher ----------------
extern "C" void kernel_launch(void* const* d_in, const int* in_sizes, int n_in,
                              void* d_out, int out_size) {
    const int*   st_ids = (const int*)d_in[0];
    const int*   dy_ids = (const int*)d_in[1];
    const int*   dy_len = (const int*)d_in[2];
    const float* st_emb = (const float*)d_in[3];
    const float* dy_emb = (const float*)d_in[4];
    const float* st_lr  = (const float*)d_in[5];
    const float* dy_lr  = (const float*)d_in[6];
    const float* bias   = (const float*)d_in[7];
    const float* bn1_g  = (const float*)d_in[8];
    const float* bn1_b  = (const float*)d_in[9];
    const float* W1     = (const float*)d_in[10];
    const float* b1     = (const float*)d_in[11];
    const float* bn2_g  = (const float*)d_in[12];
    const float* bn2_b  = (const float*)d_in[13];
    const float* W2     = (const float*)d_in[14];
    const float* b2     = (const float*)d_in[15];
    const float* bn3_g  = (const float*)d_in[16];
    const float* bn3_b  = (const float*)d_in[17];
    const float* W3     = (const float*)d_in[18];
    const float* b3     = (const float*)d_in[19];
    float* out = (float*)d_out;

    __half *x, *w1t, *h1, *w2t;
    float *lr, *ps1, *pq1, *sc1, *t1, *bp1, *b1p, *cpar;
    float *ps2, *pq2, *sc2, *t2, *bp2, *b2p, *h2;
    float *ps3, *pq3, *sc3, *t3, *coeff, *cpart;
    int* tilecnt;
    cudaGetSymbolAddress((void**)&x,    d_x);
    cudaGetSymbolAddress((void**)&lr,   d_lr);
    cudaGetSymbolAddress((void**)&ps1,  d_ps1);   cudaGetSymbolAddress((void**)&pq1,  d_pq1);
    cudaGetSymbolAddress((void**)&sc1,  d_sc1);   cudaGetSymbolAddress((void**)&t1,   d_t1);
    cudaGetSymbolAddress((void**)&w1t,  d_w1t);
    cudaGetSymbolAddress((void**)&bp1,  d_bp1);   cudaGetSymbolAddress((void**)&b1p,  d_b1p);
    cudaGetSymbolAddress((void**)&h1,   d_h1);
    cudaGetSymbolAddress((void**)&cpar, d_cpar);
    cudaGetSymbolAddress((void**)&tilecnt, d_tilecnt);
    cudaGetSymbolAddress((void**)&ps2,  d_ps2);   cudaGetSymbolAddress((void**)&pq2,  d_pq2);
    cudaGetSymbolAddress((void**)&sc2,  d_sc2);   cudaGetSymbolAddress((void**)&t2,   d_t2);
    cudaGetSymbolAddress((void**)&w2t,  d_w2t);
    cudaGetSymbolAddress((void**)&bp2,  d_bp2);   cudaGetSymbolAddress((void**)&b2p,  d_b2p);
    cudaGetSymbolAddress((void**)&h2,   d_h2);
    cudaGetSymbolAddress((void**)&ps3,  d_ps3);   cudaGetSymbolAddress((void**)&pq3,  d_pq3);
    cudaGetSymbolAddress((void**)&sc3,  d_sc3);   cudaGetSymbolAddress((void**)&t3,   d_t3);
    cudaGetSymbolAddress((void**)&coeff, d_coeff);
    cudaGetSymbolAddress((void**)&cpart, d_cpart);

    cudaFuncSetAttribute(k_mma, cudaFuncAttributeMaxDynamicSharedMemorySize, SMEM_MMA_BYTES);

    // 1) gather + pair products (fp16, x64 scale) + lr
    k_gather<<<BATCH, 640>>>(st_ids, dy_ids, dy_len, st_emb, dy_emb, st_lr, dy_lr, x, lr);
    // 2) BN1 stats (undo x64); transpose W1 (sc1/64 folded, fused bias partials)
    k_colstat_part_h<<<dim3(28, 16), 256>>>(x, ps1, pq1, DIN, KPAD1, 1.0f / XSCALE);
    k_colstat_final<<<28, 256>>>(ps1, pq1, bn1_g, bn1_b, sc1, t1, DIN);
    k_transpose_split<<<dim3(KPAD1 / 32, HID / 32), dim3(32, 8)>>>(W1, sc1, t1, DIN, KPAD1,
                                                                   1.0f / XSCALE, w1t, bp1);
    k_bias_final<<<1, 512>>>(b1, bp1, b1p, KPAD1 / 32);
    // 3) h1 = relu(x @ W1p + b1p): split-K x2 fp16 MMA, fused last-CTA epilogue (fp16 out)
    k_mma<<<dim3(4, 32, 2), 256, SMEM_MMA_BYTES>>>(x, w1t, cpar, b1p, h1, nullptr,
                                                   tilecnt, KPAD1, (KPAD1 / BK) / 2);
    // 4) BN2 stats + transpose W2 + bias
    k_colstat_part_h<<<dim3(2, 16), 256>>>(h1, ps2, pq2, HID, HID, 1.0f);
    k_colstat_final<<<2, 256>>>(ps2, pq2, bn2_g, bn2_b, sc2, t2, HID);
    k_transpose_split<<<dim3(HID / 32, HID / 32), dim3(32, 8)>>>(W2, sc2, t2, HID, HID,
                                                                 1.0f, w2t, bp2);
    k_bias_final<<<1, 512>>>(b2, bp2, b2p, HID / 32);
    // 5) h2 = relu(h1 @ W2p + b2p): split-K x2 fp16 MMA, fused epilogue (fp32 out)
    k_mma<<<dim3(4, 32, 2), 256, SMEM_MMA_BYTES>>>(h1, w2t, cpar, b2p, nullptr, h2,
                                                   tilecnt, HID, (HID / BK) / 2);
    // 6) BN3 stats + collapsed GEMM3 coefficients
    k_colstat_part<<<dim3(2, 16), 256>>>(h2, ps3, pq3, HID);
    k_colstat_final<<<2, 256>>>(ps3, pq3, bn3_g, bn3_b, sc3, t3, HID);
    k_coeff<<<HID, 128>>>(W3, sc3, t3, coeff, cpart);
    // 7) scores
    k_scores<<<BATCH / 8, 256>>>(h2, lr, coeff, cpart, b3, bias, out);
}

// round 16
// speedup vs baseline: 1.0354x; 1.0354x over previous
#include <cuda_runtime.h>
#include <cuda_fp16.h>
#include <cstdint>

// ---------------- problem constants ----------------
#define BATCH 4096
#define FST   20
#define FDY   10
#define MLEN  50
#define EDIM  16
#define FALL  30
#define PAIRS 435
#define DIN   6960          // PAIRS * EDIM
#define KPAD1 7040          // DIN padded to 64*110 (split-K 2 x 55)
#define HID   512
#define BN_EPS 1e-5f
#define XSCALE 64.0f        // fp16 subnormal guard: x stored as 64*x, W1 folded /64

// ---------------- device scratch (static, no allocation) ----------------
__device__ __align__(256) __half d_x[(size_t)BATCH * KPAD1];       // 64*x, fp16
__device__ float d_lr[BATCH];

__device__ float d_ps1[16 * DIN], d_pq1[16 * DIN];
__device__ float d_sc1[DIN], d_t1[DIN];
__device__ __align__(256) __half d_w1t[(size_t)HID * KPAD1];       // sc1*W1/64, [N][K]
__device__ float d_bp1[220 * HID];
__device__ float d_b1p[HID];
__device__ __align__(256) __half d_h1[(size_t)BATCH * HID];

__device__ __align__(256) float d_cpar[2 * (size_t)BATCH * HID];   // split-K partials

__device__ float d_ps2[16 * HID], d_pq2[16 * HID];
__device__ float d_sc2[HID], d_t2[HID];
__device__ __align__(256) __half d_w2t[(size_t)HID * HID];
__device__ float d_bp2[16 * HID];
__device__ float d_b2p[HID];
__device__ __align__(256) float d_h2[(size_t)BATCH * HID];

__device__ float d_ps3[16 * HID], d_pq3[16 * HID];
__device__ float d_sc3[HID], d_t3[HID];
__device__ float d_coeff[HID], d_cpart[HID];

// ---------------- portable PTX helpers ----------------
__device__ __forceinline__ uint32_t smem_u32(const void* p) {
    uint32_t a;
    asm("{ .reg .u64 t; cvta.to.shared.u64 t, %1; cvt.u32.u64 %0, t; }" : "=r"(a) : "l"(p));
    return a;
}
#define CP16(s, g)  asm volatile("cp.async.cg.shared.global [%0], [%1], 16;" :: "r"(s), "l"(g) : "memory")
#define CP_COMMIT() asm volatile("cp.async.commit_group;" ::: "memory")

__device__ __forceinline__ void hmma16816(float* c, const uint32_t* a, const uint32_t* b) {
    asm volatile(
        "mma.sync.aligned.m16n8k16.row.col.f32.f16.f16.f32 "
        "{%0,%1,%2,%3}, {%4,%5,%6,%7}, {%8,%9}, {%0,%1,%2,%3};"
        : "+f"(c[0]), "+f"(c[1]), "+f"(c[2]), "+f"(c[3])
        : "r"(a[0]), "r"(a[1]), "r"(a[2]), "r"(a[3]), "r"(b[0]), "r"(b[1]));
}

// ---------------- K1: gather + dyn-mean + lr + pair products -------------
// phase 2: one pair per thread, 8x LDS.128 + 2x 16B STG (vectorized)
__global__ void k_gather(const int* __restrict__ st_ids, const int* __restrict__ dy_ids,
                         const int* __restrict__ dy_len,
                         const float* __restrict__ st_emb, const float* __restrict__ dy_emb,
                         const float* __restrict__ st_lr, const float* __restrict__ dy_lr,
                         __half* __restrict__ xout, float* __restrict__ lr_out) {
    __shared__ float semb[FALL * EDIM];
    __shared__ float slr[FALL];
    int b = blockIdx.x, t = threadIdx.x;

    // pair index for this thread (registers only; used in phase 2)
    int ir = 0, jr = 0;
    if (t < PAIRS) {
        int p = t, i = 0, rem = FALL - 1;
        while (p >= rem) { p -= rem; i++; rem--; }
        ir = i;
        jr = i + 1 + p;
    }
    if (t < FST * EDIM) {                       // static fields (warps 0-9)
        int f = t >> 4, e = t & 15;
        int id = st_ids[b * FST + f];
        semb[t] = st_emb[id * EDIM + e];
        if (e == 0) slr[f] = st_lr[id];
    } else if (t < FALL * EDIM + FDY * EDIM) {  // dynamic: 2 lanes per (f,e)
        int u = t - FST * EDIM;                 // 0..319, one warp per field
        int f = u >> 5;
        int v = u & 31;
        int e = v & 15, half = v >> 4;
        int len = dy_len[b * FDY + f];
        if (len < 1) len = 1;
        const int* ids = dy_ids + ((size_t)b * FDY + f) * MLEN;
        float acc = 0.f, lacc = 0.f;
        #pragma unroll 4
        for (int m = half; m < len; m += 2) {
            int id = ids[m];
            acc += dy_emb[(size_t)id * EDIM + e];
            if (e == 0) lacc += dy_lr[id];
        }
        float acc2  = acc  + __shfl_xor_sync(0xFFFFFFFFu, acc, 16);
        float lacc2 = lacc + __shfl_xor_sync(0xFFFFFFFFu, lacc, 16);
        if (v < 16) {
            semb[(FST + f) * EDIM + e] = acc2 / (float)len;
            if (e == 0) slr[FST + f] = lacc2;
        }
    }
    __syncthreads();

    __half* xr = xout + (size_t)b * KPAD1;
    if (t < PAIRS) {
        const float4* ra = reinterpret_cast<const float4*>(semb + ir * EDIM);
        const float4* rb = reinterpret_cast<const float4*>(semb + jr * EDIM);
        uint4 outw[2];
        __half2* oh = reinterpret_cast<__half2*>(outw);
        #pragma unroll
        for (int q = 0; q < 4; q++) {
            float4 a4 = ra[q], b4 = rb[q];
            oh[2 * q + 0] = __floats2half2_rn(a4.x * b4.x * XSCALE, a4.y * b4.y * XSCALE);
            oh[2 * q + 1] = __floats2half2_rn(a4.z * b4.z * XSCALE, a4.w * b4.w * XSCALE);
        }
        *(uint4*)(xr + t * 16)     = outw[0];
        *(uint4*)(xr + t * 16 + 8) = outw[1];
    } else if (t < PAIRS + 5) {                 // zero pad region [DIN, KPAD1)
        uint4 z = {0u, 0u, 0u, 0u};
        *(uint4*)(xr + DIN + (t - PAIRS) * 16)     = z;
        *(uint4*)(xr + DIN + (t - PAIRS) * 16 + 8) = z;
    }
    if (t == 0) {
        float s = 0.f;
        #pragma unroll
        for (int f = 0; f < FALL; f++) s += slr[f];
        lr_out[b] = s;
    }
}

// ---------------- column stats over an fp16 plane (scaled) ---------------
__global__ void k_colstat_part_h(const __half* __restrict__ X,
                                 float* __restrict__ psum, float* __restrict__ psq,
                                 int ncol, int pitch, float scale) {
    int c = blockIdx.x * blockDim.x + threadIdx.x;
    if (c >= ncol) return;
    const int ROWS = BATCH / 16;
    size_t base = (size_t)blockIdx.y * ROWS * pitch + c;
    float s = 0.f, q = 0.f;
    for (int r = 0; r < ROWS; r++) {
        float v = __half2float(X[base + (size_t)r * pitch]) * scale;
        s += v; q += v * v;
    }
    psum[blockIdx.y * ncol + c] = s;
    psq[blockIdx.y * ncol + c] = q;
}

// fp32 variant (for h2)
__global__ void k_colstat_part(const float* __restrict__ X, float* __restrict__ psum,
                               float* __restrict__ psq, int ncol) {
    int c = blockIdx.x * blockDim.x + threadIdx.x;
    if (c >= ncol) return;
    const int ROWS = BATCH / 16;
    const float* p = X + (size_t)blockIdx.y * ROWS * ncol + c;
    float s = 0.f, q = 0.f;
    for (int r = 0; r < ROWS; r++) {
        float v = p[(size_t)r * ncol];
        s += v; q += v * v;
    }
    psum[blockIdx.y * ncol + c] = s;
    psq[blockIdx.y * ncol + c] = q;
}

__global__ void k_colstat_final(const float* __restrict__ psum, const float* __restrict__ psq,
                                const float* __restrict__ g, const float* __restrict__ bb,
                                float* __restrict__ sc, float* __restrict__ tsh, int ncol) {
    int c = blockIdx.x * blockDim.x + threadIdx.x;
    if (c >= ncol) return;
    float s = 0.f, q = 0.f;
    #pragma unroll
    for (int p = 0; p < 16; p++) { s += psum[p * ncol + c]; q += psq[p * ncol + c]; }
    float m = s * (1.f / BATCH);
    float v = q * (1.f / BATCH) - m * m;
    float scale = g[c] * rsqrtf(v + BN_EPS);
    sc[c]  = scale;
    tsh[c] = bb[c] - scale * m;
}

// ---------------- transpose + BN-scale + fp16 + bias partials ------------
__global__ void k_transpose_split(const float* __restrict__ W, const float* __restrict__ sc,
                                  const float* __restrict__ tsh, int Kdim, int Kpad,
                                  float wscale, __half* __restrict__ Wt,
                                  float* __restrict__ bpart) {
    __shared__ float tile[32][33];
    __shared__ float bred[8][32];
    int d0 = blockIdx.x * 32, h0 = blockIdx.y * 32;
    int tx = threadIdx.x, ty0 = threadIdx.y;
    float bacc = 0.f;
    for (int yy = ty0; yy < 32; yy += 8) {
        int d = d0 + yy;
        float w = 0.f, scl = 0.f, ts = 0.f;
        if (d < Kdim) {
            w = W[(size_t)d * HID + h0 + tx];
            scl = sc[d]; ts = tsh[d];
        }
        tile[yy][tx] = w * scl * wscale;
        bacc += ts * w;
    }
    bred[ty0][tx] = bacc;
    __syncthreads();
    for (int yy = ty0; yy < 32; yy += 8) {
        int h = h0 + yy, d = d0 + tx;
        Wt[(size_t)h * Kpad + d] = __float2half(tile[tx][yy]);
    }
    if (ty0 == 0) {
        float s = 0.f;
        #pragma unroll
        for (int r = 0; r < 8; r++) s += bred[r][tx];
        bpart[(size_t)blockIdx.x * HID + h0 + tx] = s;
    }
}

__global__ void k_bias_final(const float* __restrict__ blin, const float* __restrict__ bpart,
                             float* __restrict__ bout, int nparts) {
    int h = threadIdx.x;
    float a = blin[h];
    for (int p = 0; p < nparts; p++) a += bpart[p * HID + h];
    bout[h] = a;
}

// ---------------- mma.sync fp16 GEMM, split-K -> fp32 partials -----------
// Cpart[z][M, N=512] = A[M, Kslice_z] @ B^T  (B stored [N][K] K-major, fp16)
// 128x128 CTA tile, BK=64, 256 threads; warp tile 32x64 (2 m16 x 8 n8).
#define BK      64
#define ROWB    144         // smem row stride bytes (128B data + 16B pad)
#define TILE_B  18432       // 128 rows * 144 B
#define STAGE_B 36864       // 2 tiles (A, B)
#define SMEM_MMA_BYTES (2 * STAGE_B)

__device__ __forceinline__ void ld_chunk(uint32_t sb, int st,
        const __half* A, const __half* B,
        int row0, int col0, int Kpad, int k0, int tid) {
    const __half* tp[2] = {A, B};
    #pragma unroll
    for (int tile = 0; tile < 2; tile++) {
        int rbase = tile ? col0 : row0;
        #pragma unroll
        for (int h = 0; h < 4; h++) {
            int ch  = tid + h * 256;          // 0..1023 (128 rows x 8 16B-chunks)
            int row = ch >> 3, c16 = ch & 7;
            uint32_t sa = sb + st * STAGE_B + tile * TILE_B + row * ROWB + c16 * 16;
            const __half* g = tp[tile] + (size_t)(rbase + row) * Kpad + k0 + c16 * 8;
            CP16(sa, g);
        }
    }
    CP_COMMIT();
}

__global__ __launch_bounds__(256, 2)
void k_mma(const __half* __restrict__ A, const __half* __restrict__ B,
           float* __restrict__ Cpart, int Kpad, int NC) {
    extern __shared__ __align__(16) char smem[];
    uint32_t sb = smem_u32(smem);
    int tid = threadIdx.x, wid = tid >> 5, lane = tid & 31;
    int row0 = blockIdx.y * 128, col0 = blockIdx.x * 128;
    int k0 = blockIdx.z * NC * BK;
    float* Cp = Cpart + (size_t)blockIdx.z * BATCH * HID;
    int wr = (wid & 3) * 32;
    int wc = (wid >> 2) * 64;
    int tq = lane >> 2;
    int tr = (lane & 3) * 2;

    float acc[2][8][4];
    #pragma unroll
    for (int i = 0; i < 2; i++)
        #pragma unroll
        for (int j = 0; j < 8; j++)
            #pragma unroll
            for (int q = 0; q < 4; q++) acc[i][j][q] = 0.f;

    ld_chunk(sb, 0, A, B, row0, col0, Kpad, k0, tid);
    ld_chunk(sb, 1, A, B, row0, col0, Kpad, k0 + BK, tid);

    for (int c = 0; c < NC; c++) {
        if (c + 1 < NC) asm volatile("cp.async.wait_group 1;" ::: "memory");
        else            asm volatile("cp.async.wait_group 0;" ::: "memory");
        __syncthreads();

        const char* st = smem + (c & 1) * STAGE_B;
        const char* As = st;
        const char* Bs = st + TILE_B;

        #pragma unroll
        for (int ks = 0; ks < 4; ks++) {
            int kk = ks * 16;
            uint32_t af[2][4], bf[8][2];
            #pragma unroll
            for (int mt = 0; mt < 2; mt++) {
                int mA = wr + mt * 16 + tq;
                af[mt][0] = *(const uint32_t*)(As + mA * ROWB + (kk + tr) * 2);
                af[mt][1] = *(const uint32_t*)(As + (mA + 8) * ROWB + (kk + tr) * 2);
                af[mt][2] = *(const uint32_t*)(As + mA * ROWB + (kk + 8 + tr) * 2);
                af[mt][3] = *(const uint32_t*)(As + (mA + 8) * ROWB + (kk + 8 + tr) * 2);
            }
            #pragma unroll
            for (int nt = 0; nt < 8; nt++) {
                int nB = wc + nt * 8 + tq;
                bf[nt][0] = *(const uint32_t*)(Bs + nB * ROWB + (kk + tr) * 2);
                bf[nt][1] = *(const uint32_t*)(Bs + nB * ROWB + (kk + 8 + tr) * 2);
            }
            #pragma unroll
            for (int mt = 0; mt < 2; mt++)
                #pragma unroll
                for (int nt = 0; nt < 8; nt++) hmma16816(acc[mt][nt], af[mt], bf[nt]);
        }
        __syncthreads();
        if (c + 2 < NC)
            ld_chunk(sb, c & 1, A, B, row0, col0, Kpad, k0 + (c + 2) * BK, tid);
    }

    #pragma unroll
    for (int mt = 0; mt < 2; mt++) {
        #pragma unroll
        for (int nt = 0; nt < 8; nt++) {
            int m = row0 + wr + mt * 16 + tq;
            int n = col0 + wc + nt * 8 + tr;
            *(float2*)(Cp + (size_t)m * HID + n)       = make_float2(acc[mt][nt][0], acc[mt][nt][1]);
            *(float2*)(Cp + (size_t)(m + 8) * HID + n) = make_float2(acc[mt][nt][2], acc[mt][nt][3]);
        }
    }
}

// ---------------- split-K epilogue: relu(p0+p1+bias) -> fp16 or fp32 -----
__global__ void k_epi(const float* __restrict__ p0, const float* __restrict__ p1,
                      const float* __restrict__ bias,
                      __half* __restrict__ OutH, float* __restrict__ OutF32) {
    size_t idx = ((size_t)blockIdx.x * blockDim.x + threadIdx.x) * 4;
    int col = (int)(idx & (HID - 1));
    float4 a = *(const float4*)(p0 + idx);
    float4 b = *(const float4*)(p1 + idx);
    float4 bi = *(const float4*)(bias + col);
    float v0 = fmaxf(a.x + b.x + bi.x, 0.f);
    float v1 = fmaxf(a.y + b.y + bi.y, 0.f);
    float v2 = fmaxf(a.z + b.z + bi.z, 0.f);
    float v3 = fmaxf(a.w + b.w + bi.w, 0.f);
    if (OutF32) {
        *(float4*)(OutF32 + idx) = make_float4(v0, v1, v2, v3);
    } else {
        __half2 h0 = __floats2half2_rn(v0, v1);
        __half2 h1 = __floats2half2_rn(v2, v3);
        *(uint2*)(OutH + idx) = make_uint2(*(uint32_t*)&h0, *(uint32_t*)&h1);
    }
}

// ---------------- GEMM3 collapsed: coeff[k] = sc3[k]*rowsum(W3[k,:]) -----
__global__ void k_coeff(const float* __restrict__ W3, const float* __restrict__ sc3,
                        const float* __restrict__ t3, float* __restrict__ coeff,
                        float* __restrict__ cpart) {
    int k = blockIdx.x, t = threadIdx.x;
    float a = 0.f;
    for (int j = t; j < HID; j += 128) a += W3[(size_t)k * HID + j];
    __shared__ float r[128];
    r[t] = a; __syncthreads();
    for (int s = 64; s > 0; s >>= 1) { if (t < s) r[t] += r[t + s]; __syncthreads(); }
    if (t == 0) {
        float w = r[0];
        coeff[k] = sc3[k] * w;
        cpart[k] = t3[k] * w;
    }
}

// ---------------- final scores ----------------
__global__ void k_scores(const float* __restrict__ h2r, const float* __restrict__ lr,
                         const float* __restrict__ coeff, const float* __restrict__ cpart,
                         const float* __restrict__ b3, const float* __restrict__ biasp,
                         float* __restrict__ out) {
    __shared__ float sco[HID];
    __shared__ float red[256];
    int t = threadIdx.x;
    sco[t] = coeff[t]; sco[t + 256] = coeff[t + 256];
    float c = cpart[t] + b3[t] + cpart[t + 256] + b3[t + 256];
    red[t] = c; __syncthreads();
    for (int s = 128; s > 0; s >>= 1) { if (t < s) red[t] += red[t + s]; __syncthreads(); }

    int warp = t >> 5, lane = t & 31;
    int row = blockIdx.x * 8 + warp;
    const float* hr = h2r + (size_t)row * HID;
    float acc = 0.f;
    #pragma unroll
    for (int k = lane; k < HID; k += 32) acc += sco[k] * hr[k];
    #pragma unroll
    for (int o = 16; o > 0; o >>= 1) acc += __shfl_xor_sync(0xFFFFFFFFu, acc, o);
    if (lane == 0) out[row] = biasp[0] + lr[row] + acc + red[0];
}

// ---------------- launcher ----------------
extern "C" void kernel_launch(void* const* d_in, const int* in_sizes, int n_in,
                              void* d_out, int out_size) {
    const int*   st_ids = (const int*)d_in[0];
    const int*   dy_ids = (const int*)d_in[1];
    const int*   dy_len = (const int*)d_in[2];
    const float* st_emb = (const float*)d_in[3];
    const float* dy_emb = (const float*)d_in[4];
    const float* st_lr  = (const float*)d_in[5];
    const float* dy_lr  = (const float*)d_in[6];
    const float* bias   = (const float*)d_in[7];
    const float* bn1_g  = (const float*)d_in[8];
    const float* bn1_b  = (const float*)d_in[9];
    const float* W1     = (const float*)d_in[10];
    const float* b1     = (const float*)d_in[11];
    const float* bn2_g  = (const float*)d_in[12];
    const float* bn2_b  = (const float*)d_in[13];
    const float* W2     = (const float*)d_in[14];
    const float* b2     = (const float*)d_in[15];
    const float* bn3_g  = (const float*)d_in[16];
    const float* bn3_b  = (const float*)d_in[17];
    const float* W3     = (const float*)d_in[18];
    const float* b3     = (const float*)d_in[19];
    float* out = (float*)d_out;

    __half *x, *w1t, *h1, *w2t;
    float *lr, *ps1, *pq1, *sc1, *t1, *bp1, *b1p, *cpar;
    float *ps2, *pq2, *sc2, *t2, *bp2, *b2p, *h2;
    float *ps3, *pq3, *sc3, *t3, *coeff, *cpart;
    cudaGetSymbolAddress((void**)&x,    d_x);
    cudaGetSymbolAddress((void**)&lr,   d_lr);
    cudaGetSymbolAddress((void**)&ps1,  d_ps1);   cudaGetSymbolAddress((void**)&pq1,  d_pq1);
    cudaGetSymbolAddress((void**)&sc1,  d_sc1);   cudaGetSymbolAddress((void**)&t1,   d_t1);
    cudaGetSymbolAddress((void**)&w1t,  d_w1t);
    cudaGetSymbolAddress((void**)&bp1,  d_bp1);   cudaGetSymbolAddress((void**)&b1p,  d_b1p);
    cudaGetSymbolAddress((void**)&h1,   d_h1);
    cudaGetSymbolAddress((void**)&cpar, d_cpar);
    cudaGetSymbolAddress((void**)&ps2,  d_ps2);   cudaGetSymbolAddress((void**)&pq2,  d_pq2);
    cudaGetSymbolAddress((void**)&sc2,  d_sc2);   cudaGetSymbolAddress((void**)&t2,   d_t2);
    cudaGetSymbolAddress((void**)&w2t,  d_w2t);
    cudaGetSymbolAddress((void**)&bp2,  d_bp2);   cudaGetSymbolAddress((void**)&b2p,  d_b2p);
    cudaGetSymbolAddress((void**)&h2,   d_h2);
    cudaGetSymbolAddress((void**)&ps3,  d_ps3);   cudaGetSymbolAddress((void**)&pq3,  d_pq3);
    cudaGetSymbolAddress((void**)&sc3,  d_sc3);   cudaGetSymbolAddress((void**)&t3,   d_t3);
    cudaGetSymbolAddress((void**)&coeff, d_coeff);
    cudaGetSymbolAddress((void**)&cpart, d_cpart);

    float* cpar1 = cpar + (size_t)BATCH * HID;

    cudaFuncSetAttribute(k_mma, cudaFuncAttributeMaxDynamicSharedMemorySize, SMEM_MMA_BYTES);

    const int EPI_BLOCKS = (BATCH * HID) / (256 * 4);

    // 1) gather + pair products (fp16, x64 scale, vectorized stores) + lr
    k_gather<<<BATCH, 640>>>(st_ids, dy_ids, dy_len, st_emb, dy_emb, st_lr, dy_lr, x, lr);
    // 2) BN1 stats (undo x64); transpose W1 (sc1/64 folded, fused bias partials)
    k_colstat_part_h<<<dim3(28, 16), 256>>>(x, ps1, pq1, DIN, KPAD1, 1.0f / XSCALE);
    k_colstat_final<<<28, 256>>>(ps1, pq1, bn1_g, bn1_b, sc1, t1, DIN);
    k_transpose_split<<<dim3(KPAD1 / 32, HID / 32), dim3(32, 8)>>>(W1, sc1, t1, DIN, KPAD1,
                                                                   1.0f / XSCALE, w1t, bp1);
    k_bias_final<<<1, 512>>>(b1, bp1, b1p, KPAD1 / 32);
    // 3) h1 = relu(x @ W1p + b1p): split-K x2 fp16 MMA (BK=64) + epilogue (fp16 out)
    k_mma<<<dim3(4, 32, 2), 256, SMEM_MMA_BYTES>>>(x, w1t, cpar, KPAD1, (KPAD1 / BK) / 2);
    k_epi<<<EPI_BLOCKS, 256>>>(cpar, cpar1, b1p, h1, nullptr);
    // 4) BN2 stats + transpose W2 + bias
    k_colstat_part_h<<<dim3(2, 16), 256>>>(h1, ps2, pq2, HID, HID, 1.0f);
    k_colstat_final<<<2, 256>>>(ps2, pq2, bn2_g, bn2_b, sc2, t2, HID);
    k_transpose_split<<<dim3(HID / 32, HID / 32), dim3(32, 8)>>>(W2, sc2, t2, HID, HID,
                                                                 1.0f, w2t, bp2);
    k_bias_final<<<1, 512>>>(b2, bp2, b2p, HID / 32);
    // 5) h2 = relu(h1 @ W2p + b2p): split-K x2 fp16 MMA + epilogue (fp32 out)
    k_mma<<<dim3(4, 32, 2), 256, SMEM_MMA_BYTES>>>(h1, w2t, cpar, HID, (HID / BK) / 2);
    k_epi<<<EPI_BLOCKS, 256>>>(cpar, cpar1, b2p, nullptr, h2);
    // 6) BN3 stats + collapsed GEMM3 coefficients
    k_colstat_part<<<dim3(2, 16), 256>>>(h2, ps3, pq3, HID);
    k_colstat_final<<<2, 256>>>(ps3, pq3, bn3_g, bn3_b, sc3, t3, HID);
    k_coeff<<<HID, 128>>>(W3, sc3, t3, coeff, cpart);
    // 7) scores
    k_scores<<<BATCH / 8, 256>>>(h2, lr, coeff, cpart, b3, bias, out);
}

// round 17
// speedup vs baseline: 1.1839x; 1.1434x over previous
#include <cuda_runtime.h>
#include <cuda_fp16.h>
#include <cstdint>

// ---------------- problem constants ----------------
#define BATCH 4096
#define FST   20
#define FDY   10
#define MLEN  50
#define EDIM  16
#define FALL  30
#define PAIRS 435
#define DIN   6960          // PAIRS * EDIM
#define KPAD1 7040          // DIN padded to 64*110 (split-K 2 x 55)
#define HID   512
#define BN_EPS 1e-5f
#define XSCALE 64.0f        // fp16 subnormal guard: x stored as 64*x, W1 folded /64

// ---------------- device scratch (static, no allocation) ----------------
__device__ __align__(256) __half d_x[(size_t)BATCH * KPAD1];       // 64*x, fp16
__device__ float d_lr[BATCH];

__device__ float d_ps1[16 * DIN], d_pq1[16 * DIN];
__device__ float d_sc1[DIN], d_t1[DIN];
__device__ __align__(256) __half d_w1t[(size_t)HID * KPAD1];       // sc1*W1/64, [N][K]
__device__ float d_bp1[220 * HID];
__device__ float d_b1p[HID];
__device__ __align__(256) __half d_h1[(size_t)BATCH * HID];

__device__ __align__(256) float d_cpar[2 * (size_t)BATCH * HID];   // split-K partials

__device__ float d_ps2[16 * HID], d_pq2[16 * HID];
__device__ float d_sc2[HID], d_t2[HID];
__device__ __align__(256) __half d_w2t[(size_t)HID * HID];
__device__ float d_bp2[16 * HID];
__device__ float d_b2p[HID];
__device__ __align__(256) float d_h2[(size_t)BATCH * HID];

__device__ float d_ps3[16 * HID], d_pq3[16 * HID];
__device__ float d_sc3[HID], d_t3[HID];
__device__ float d_coeff[HID], d_cpart[HID];

// ---------------- portable PTX helpers ----------------
__device__ __forceinline__ uint32_t smem_u32(const void* p) {
    uint32_t a;
    asm("{ .reg .u64 t; cvta.to.shared.u64 t, %1; cvt.u32.u64 %0, t; }" : "=r"(a) : "l"(p));
    return a;
}
#define CP16(s, g)  asm volatile("cp.async.cg.shared.global [%0], [%1], 16;" :: "r"(s), "l"(g) : "memory")
#define CP_COMMIT() asm volatile("cp.async.commit_group;" ::: "memory")

#define LDM4(r, addr) \
    asm volatile("ldmatrix.sync.aligned.m8n8.x4.shared.b16 {%0,%1,%2,%3}, [%4];" \
        : "=r"((r)[0]), "=r"((r)[1]), "=r"((r)[2]), "=r"((r)[3]) : "r"(addr))

__device__ __forceinline__ void hmma16816(float* c, const uint32_t* a, const uint32_t* b) {
    asm volatile(
        "mma.sync.aligned.m16n8k16.row.col.f32.f16.f16.f32 "
        "{%0,%1,%2,%3}, {%4,%5,%6,%7}, {%8,%9}, {%0,%1,%2,%3};"
        : "+f"(c[0]), "+f"(c[1]), "+f"(c[2]), "+f"(c[3])
        : "r"(a[0]), "r"(a[1]), "r"(a[2]), "r"(a[3]), "r"(b[0]), "r"(b[1]));
}

// ---------------- K1: gather + dyn-mean + lr + pair products -------------
// (R12-proven version: strided coalesced phase-2 stores)
__global__ void k_gather(const int* __restrict__ st_ids, const int* __restrict__ dy_ids,
                         const int* __restrict__ dy_len,
                         const float* __restrict__ st_emb, const float* __restrict__ dy_emb,
                         const float* __restrict__ st_lr, const float* __restrict__ dy_lr,
                         __half* __restrict__ xout, float* __restrict__ lr_out) {
    __shared__ float semb[FALL * EDIM];
    __shared__ float slr[FALL];
    __shared__ unsigned char ci[PAIRS], cj[PAIRS];
    int b = blockIdx.x, t = threadIdx.x;

    if (t < PAIRS) {
        int p = t, i = 0, rem = FALL - 1;
        while (p >= rem) { p -= rem; i++; rem--; }
        ci[t] = (unsigned char)i;
        cj[t] = (unsigned char)(i + 1 + p);
    }
    if (t < FST * EDIM) {                       // static fields (warps 0-9)
        int f = t >> 4, e = t & 15;
        int id = st_ids[b * FST + f];
        semb[t] = st_emb[id * EDIM + e];
        if (e == 0) slr[f] = st_lr[id];
    } else if (t < FALL * EDIM + FDY * EDIM) {  // dynamic: 2 lanes per (f,e)
        int u = t - FST * EDIM;                 // 0..319, one warp per field
        int f = u >> 5;
        int v = u & 31;
        int e = v & 15, half = v >> 4;
        int len = dy_len[b * FDY + f];
        if (len < 1) len = 1;
        const int* ids = dy_ids + ((size_t)b * FDY + f) * MLEN;
        float acc = 0.f, lacc = 0.f;
        #pragma unroll 4
        for (int m = half; m < len; m += 2) {
            int id = ids[m];
            acc += dy_emb[(size_t)id * EDIM + e];
            if (e == 0) lacc += dy_lr[id];
        }
        float acc2  = acc  + __shfl_xor_sync(0xFFFFFFFFu, acc, 16);
        float lacc2 = lacc + __shfl_xor_sync(0xFFFFFFFFu, lacc, 16);
        if (v < 16) {
            semb[(FST + f) * EDIM + e] = acc2 / (float)len;
            if (e == 0) slr[FST + f] = lacc2;
        }
    }
    __syncthreads();

    __half* xr = xout + (size_t)b * KPAD1;
    for (int idx = t; idx < KPAD1; idx += 640) {
        float v = 0.f;
        if (idx < DIN) {
            int p = idx >> 4, e = idx & 15;
            v = semb[ci[p] * EDIM + e] * semb[cj[p] * EDIM + e];
        }
        xr[idx] = __float2half(v * XSCALE);
    }
    if (t == 0) {
        float s = 0.f;
        #pragma unroll
        for (int f = 0; f < FALL; f++) s += slr[f];
        lr_out[b] = s;
    }
}

// ---------------- column stats over an fp16 plane (scaled) ---------------
__global__ void k_colstat_part_h(const __half* __restrict__ X,
                                 float* __restrict__ psum, float* __restrict__ psq,
                                 int ncol, int pitch, float scale) {
    int c = blockIdx.x * blockDim.x + threadIdx.x;
    if (c >= ncol) return;
    const int ROWS = BATCH / 16;
    size_t base = (size_t)blockIdx.y * ROWS * pitch + c;
    float s = 0.f, q = 0.f;
    for (int r = 0; r < ROWS; r++) {
        float v = __half2float(X[base + (size_t)r * pitch]) * scale;
        s += v; q += v * v;
    }
    psum[blockIdx.y * ncol + c] = s;
    psq[blockIdx.y * ncol + c] = q;
}

// fp32 variant (for h2)
__global__ void k_colstat_part(const float* __restrict__ X, float* __restrict__ psum,
                               float* __restrict__ psq, int ncol) {
    int c = blockIdx.x * blockDim.x + threadIdx.x;
    if (c >= ncol) return;
    const int ROWS = BATCH / 16;
    const float* p = X + (size_t)blockIdx.y * ROWS * ncol + c;
    float s = 0.f, q = 0.f;
    for (int r = 0; r < ROWS; r++) {
        float v = p[(size_t)r * ncol];
        s += v; q += v * v;
    }
    psum[blockIdx.y * ncol + c] = s;
    psq[blockIdx.y * ncol + c] = q;
}

__global__ void k_colstat_final(const float* __restrict__ psum, const float* __restrict__ psq,
                                const float* __restrict__ g, const float* __restrict__ bb,
                                float* __restrict__ sc, float* __restrict__ tsh, int ncol) {
    int c = blockIdx.x * blockDim.x + threadIdx.x;
    if (c >= ncol) return;
    float s = 0.f, q = 0.f;
    #pragma unroll
    for (int p = 0; p < 16; p++) { s += psum[p * ncol + c]; q += psq[p * ncol + c]; }
    float m = s * (1.f / BATCH);
    float v = q * (1.f / BATCH) - m * m;
    float scale = g[c] * rsqrtf(v + BN_EPS);
    sc[c]  = scale;
    tsh[c] = bb[c] - scale * m;
}

// ---------------- transpose + BN-scale + fp16 + bias partials ------------
__global__ void k_transpose_split(const float* __restrict__ W, const float* __restrict__ sc,
                                  const float* __restrict__ tsh, int Kdim, int Kpad,
                                  float wscale, __half* __restrict__ Wt,
                                  float* __restrict__ bpart) {
    __shared__ float tile[32][33];
    __shared__ float bred[8][32];
    int d0 = blockIdx.x * 32, h0 = blockIdx.y * 32;
    int tx = threadIdx.x, ty0 = threadIdx.y;
    float bacc = 0.f;
    for (int yy = ty0; yy < 32; yy += 8) {
        int d = d0 + yy;
        float w = 0.f, scl = 0.f, ts = 0.f;
        if (d < Kdim) {
            w = W[(size_t)d * HID + h0 + tx];
            scl = sc[d]; ts = tsh[d];
        }
        tile[yy][tx] = w * scl * wscale;
        bacc += ts * w;
    }
    bred[ty0][tx] = bacc;
    __syncthreads();
    for (int yy = ty0; yy < 32; yy += 8) {
        int h = h0 + yy, d = d0 + tx;
        Wt[(size_t)h * Kpad + d] = __float2half(tile[tx][yy]);
    }
    if (ty0 == 0) {
        float s = 0.f;
        #pragma unroll
        for (int r = 0; r < 8; r++) s += bred[r][tx];
        bpart[(size_t)blockIdx.x * HID + h0 + tx] = s;
    }
}

__global__ void k_bias_final(const float* __restrict__ blin, const float* __restrict__ bpart,
                             float* __restrict__ bout, int nparts) {
    int h = threadIdx.x;
    float a = blin[h];
    for (int p = 0; p < nparts; p++) a += bpart[p * HID + h];
    bout[h] = a;
}

// ---------------- mma.sync fp16 GEMM, split-K -> fp32 partials -----------
// Cpart[z][M, N=512] = A[M, Kslice_z] @ B^T  (B stored [N][K] K-major, fp16)
// 128x128 CTA tile, BK=64, 256 threads; warp tile 32x64 (2 m16 x 8 n8).
// ldmatrix.x4 fragment loads (mapping validated in R7); conflict-free at ROWB=144.
#define BK      64
#define ROWB    144         // smem row stride bytes (128B data + 16B pad)
#define TILE_B  18432       // 128 rows * 144 B
#define STAGE_B 36864       // 2 tiles (A, B)
#define SMEM_MMA_BYTES (2 * STAGE_B)

__device__ __forceinline__ void ld_chunk(uint32_t sb, int st,
        const __half* A, const __half* B,
        int row0, int col0, int Kpad, int k0, int tid) {
    const __half* tp[2] = {A, B};
    #pragma unroll
    for (int tile = 0; tile < 2; tile++) {
        int rbase = tile ? col0 : row0;
        #pragma unroll
        for (int h = 0; h < 4; h++) {
            int ch  = tid + h * 256;          // 0..1023 (128 rows x 8 16B-chunks)
            int row = ch >> 3, c16 = ch & 7;
            uint32_t sa = sb + st * STAGE_B + tile * TILE_B + row * ROWB + c16 * 16;
            const __half* g = tp[tile] + (size_t)(rbase + row) * Kpad + k0 + c16 * 8;
            CP16(sa, g);
        }
    }
    CP_COMMIT();
}

__global__ __launch_bounds__(256, 2)
void k_mma(const __half* __restrict__ A, const __half* __restrict__ B,
           float* __restrict__ Cpart, int Kpad, int NC) {
    extern __shared__ __align__(16) char smem[];
    uint32_t sb = smem_u32(smem);
    int tid = threadIdx.x, wid = tid >> 5, lane = tid & 31;
    int row0 = blockIdx.y * 128, col0 = blockIdx.x * 128;
    int k0 = blockIdx.z * NC * BK;
    float* Cp = Cpart + (size_t)blockIdx.z * BATCH * HID;
    int wr = (wid & 3) * 32;
    int wc = (wid >> 2) * 64;
    int tq = lane >> 2;
    int tr = (lane & 3) * 2;

    // ldmatrix per-thread byte offsets within a tile (R7-validated mapping)
    int aRowSel = (lane & 7) + ((lane >> 3) & 1) * 8;
    int aColSel = (lane >> 4) * 8;           // k element offset 0/8
    int bRowSel = (lane & 7) + ((lane >> 4) & 1) * 8;
    int bColSel = ((lane >> 3) & 1) * 8;
    uint32_t offA[2], offB[4];
    #pragma unroll
    for (int mt = 0; mt < 2; mt++)
        offA[mt] = (wr + mt * 16 + aRowSel) * ROWB + aColSel * 2;
    #pragma unroll
    for (int np = 0; np < 4; np++)
        offB[np] = (wc + np * 16 + bRowSel) * ROWB + bColSel * 2;

    float acc[2][8][4];
    #pragma unroll
    for (int i = 0; i < 2; i++)
        #pragma unroll
        for (int j = 0; j < 8; j++)
            #pragma unroll
            for (int q = 0; q < 4; q++) acc[i][j][q] = 0.f;

    ld_chunk(sb, 0, A, B, row0, col0, Kpad, k0, tid);
    ld_chunk(sb, 1, A, B, row0, col0, Kpad, k0 + BK, tid);

    for (int c = 0; c < NC; c++) {
        if (c + 1 < NC) asm volatile("cp.async.wait_group 1;" ::: "memory");
        else            asm volatile("cp.async.wait_group 0;" ::: "memory");
        __syncthreads();

        uint32_t base = sb + (c & 1) * STAGE_B;

        #pragma unroll
        for (int ks = 0; ks < 4; ks++) {
            int kb = ks * 32;       // 16 elements * 2 bytes
            uint32_t af[2][4], bq[4][4];
            #pragma unroll
            for (int mt = 0; mt < 2; mt++) LDM4(af[mt], base + offA[mt] + kb);
            #pragma unroll
            for (int np = 0; np < 4; np++) LDM4(bq[np], base + TILE_B + offB[np] + kb);
            #pragma unroll
            for (int mt = 0; mt < 2; mt++)
                #pragma unroll
                for (int np = 0; np < 4; np++) {
                    hmma16816(acc[mt][2 * np],     af[mt], &bq[np][0]);
                    hmma16816(acc[mt][2 * np + 1], af[mt], &bq[np][2]);
                }
        }
        __syncthreads();
        if (c + 2 < NC)
            ld_chunk(sb, c & 1, A, B, row0, col0, Kpad, k0 + (c + 2) * BK, tid);
    }

    #pragma unroll
    for (int mt = 0; mt < 2; mt++) {
        #pragma unroll
        for (int nt = 0; nt < 8; nt++) {
            int m = row0 + wr + mt * 16 + tq;
            int n = col0 + wc + nt * 8 + tr;
            *(float2*)(Cp + (size_t)m * HID + n)       = make_float2(acc[mt][nt][0], acc[mt][nt][1]);
            *(float2*)(Cp + (size_t)(m + 8) * HID + n) = make_float2(acc[mt][nt][2], acc[mt][nt][3]);
        }
    }
}

// ---------------- split-K epilogue: relu(p0+p1+bias) -> fp16 or fp32 -----
__global__ void k_epi(const float* __restrict__ p0, const float* __restrict__ p1,
                      const float* __restrict__ bias,
                      __half* __restrict__ OutH, float* __restrict__ OutF32) {
    size_t idx = ((size_t)blockIdx.x * blockDim.x + threadIdx.x) * 4;
    int col = (int)(idx & (HID - 1));
    float4 a = *(const float4*)(p0 + idx);
    float4 b = *(const float4*)(p1 + idx);
    float4 bi = *(const float4*)(bias + col);
    float v0 = fmaxf(a.x + b.x + bi.x, 0.f);
    float v1 = fmaxf(a.y + b.y + bi.y, 0.f);
    float v2 = fmaxf(a.z + b.z + bi.z, 0.f);
    float v3 = fmaxf(a.w + b.w + bi.w, 0.f);
    if (OutF32) {
        *(float4*)(OutF32 + idx) = make_float4(v0, v1, v2, v3);
    } else {
        __half2 h0 = __floats2half2_rn(v0, v1);
        __half2 h1 = __floats2half2_rn(v2, v3);
        *(uint2*)(OutH + idx) = make_uint2(*(uint32_t*)&h0, *(uint32_t*)&h1);
    }
}

// ---------------- GEMM3 collapsed: coeff[k] = sc3[k]*rowsum(W3[k,:]) -----
__global__ void k_coeff(const float* __restrict__ W3, const float* __restrict__ sc3,
                        const float* __restrict__ t3, float* __restrict__ coeff,
                        float* __restrict__ cpart) {
    int k = blockIdx.x, t = threadIdx.x;
    float a = 0.f;
    for (int j = t; j < HID; j += 128) a += W3[(size_t)k * HID + j];
    __shared__ float r[128];
    r[t] = a; __syncthreads();
    for (int s = 64; s > 0; s >>= 1) { if (t < s) r[t] += r[t + s]; __syncthreads(); }
    if (t == 0) {
        float w = r[0];
        coeff[k] = sc3[k] * w;
        cpart[k] = t3[k] * w;
    }
}

// ---------------- final scores ----------------
__global__ void k_scores(const float* __restrict__ h2r, const float* __restrict__ lr,
                         const float* __restrict__ coeff, const float* __restrict__ cpart,
                         const float* __restrict__ b3, const float* __restrict__ biasp,
                         float* __restrict__ out) {
    __shared__ float sco[HID];
    __shared__ float red[256];
    int t = threadIdx.x;
    sco[t] = coeff[t]; sco[t + 256] = coeff[t + 256];
    float c = cpart[t] + b3[t] + cpart[t + 256] + b3[t + 256];
    red[t] = c; __syncthreads();
    for (int s = 128; s > 0; s >>= 1) { if (t < s) red[t] += red[t + s]; __syncthreads(); }

    int warp = t >> 5, lane = t & 31;
    int row = blockIdx.x * 8 + warp;
    const float* hr = h2r + (size_t)row * HID;
    float acc = 0.f;
    #pragma unroll
    for (int k = lane; k < HID; k += 32) acc += sco[k] * hr[k];
    #pragma unroll
    for (int o = 16; o > 0; o >>= 1) acc += __shfl_xor_sync(0xFFFFFFFFu, acc, o);
    if (lane == 0) out[row] = biasp[0] + lr[row] + acc + red[0];
}

// ---------------- launcher ----------------
extern "C" void kernel_launch(void* const* d_in, const int* in_sizes, int n_in,
                              void* d_out, int out_size) {
    const int*   st_ids = (const int*)d_in[0];
    const int*   dy_ids = (const int*)d_in[1];
    const int*   dy_len = (const int*)d_in[2];
    const float* st_emb = (const float*)d_in[3];
    const float* dy_emb = (const float*)d_in[4];
    const float* st_lr  = (const float*)d_in[5];
    const float* dy_lr  = (const float*)d_in[6];
    const float* bias   = (const float*)d_in[7];
    const float* bn1_g  = (const float*)d_in[8];
    const float* bn1_b  = (const float*)d_in[9];
    const float* W1     = (const float*)d_in[10];
    const float* b1     = (const float*)d_in[11];
    const float* bn2_g  = (const float*)d_in[12];
    const float* bn2_b  = (const float*)d_in[13];
    const float* W2     = (const float*)d_in[14];
    const float* b2     = (const float*)d_in[15];
    const float* bn3_g  = (const float*)d_in[16];
    const float* bn3_b  = (const float*)d_in[17];
    const float* W3     = (const float*)d_in[18];
    const float* b3     = (const float*)d_in[19];
    float* out = (float*)d_out;

    __half *x, *w1t, *h1, *w2t;
    float *lr, *ps1, *pq1, *sc1, *t1, *bp1, *b1p, *cpar;
    float *ps2, *pq2, *sc2, *t2, *bp2, *b2p, *h2;
    float *ps3, *pq3, *sc3, *t3, *coeff, *cpart;
    cudaGetSymbolAddress((void**)&x,    d_x);
    cudaGetSymbolAddress((void**)&lr,   d_lr);
    cudaGetSymbolAddress((void**)&ps1,  d_ps1);   cudaGetSymbolAddress((void**)&pq1,  d_pq1);
    cudaGetSymbolAddress((void**)&sc1,  d_sc1);   cudaGetSymbolAddress((void**)&t1,   d_t1);
    cudaGetSymbolAddress((void**)&w1t,  d_w1t);
    cudaGetSymbolAddress((void**)&bp1,  d_bp1);   cudaGetSymbolAddress((void**)&b1p,  d_b1p);
    cudaGetSymbolAddress((void**)&h1,   d_h1);
    cudaGetSymbolAddress((void**)&cpar, d_cpar);
    cudaGetSymbolAddress((void**)&ps2,  d_ps2);   cudaGetSymbolAddress((void**)&pq2,  d_pq2);
    cudaGetSymbolAddress((void**)&sc2,  d_sc2);   cudaGetSymbolAddress((void**)&t2,   d_t2);
    cudaGetSymbolAddress((void**)&w2t,  d_w2t);
    cudaGetSymbolAddress((void**)&bp2,  d_bp2);   cudaGetSymbolAddress((void**)&b2p,  d_b2p);
    cudaGetSymbolAddress((void**)&h2,   d_h2);
    cudaGetSymbolAddress((void**)&ps3,  d_ps3);   cudaGetSymbolAddress((void**)&pq3,  d_pq3);
    cudaGetSymbolAddress((void**)&sc3,  d_sc3);   cudaGetSymbolAddress((void**)&t3,   d_t3);
    cudaGetSymbolAddress((void**)&coeff, d_coeff);
    cudaGetSymbolAddress((void**)&cpart, d_cpart);

    float* cpar1 = cpar + (size_t)BATCH * HID;

    cudaFuncSetAttribute(k_mma, cudaFuncAttributeMaxDynamicSharedMemorySize, SMEM_MMA_BYTES);

    const int EPI_BLOCKS = (BATCH * HID) / (256 * 4);

    // 1) gather + pair products (fp16, x64 scale) + lr
    k_gather<<<BATCH, 640>>>(st_ids, dy_ids, dy_len, st_emb, dy_emb, st_lr, dy_lr, x, lr);
    // 2) BN1 stats (undo x64); transpose W1 (sc1/64 folded, fused bias partials)
    k_colstat_part_h<<<dim3(28, 16), 256>>>(x, ps1, pq1, DIN, KPAD1, 1.0f / XSCALE);
    k_colstat_final<<<28, 256>>>(ps1, pq1, bn1_g, bn1_b, sc1, t1, DIN);
    k_transpose_split<<<dim3(KPAD1 / 32, HID / 32), dim3(32, 8)>>>(W1, sc1, t1, DIN, KPAD1,
                                                                   1.0f / XSCALE, w1t, bp1);
    k_bias_final<<<1, 512>>>(b1, bp1, b1p, KPAD1 / 32);
    // 3) h1 = relu(x @ W1p + b1p): split-K x2 fp16 MMA (BK=64, ldmatrix) + epilogue (fp16 out)
    k_mma<<<dim3(4, 32, 2), 256, SMEM_MMA_BYTES>>>(x, w1t, cpar, KPAD1, (KPAD1 / BK) / 2);
    k_epi<<<EPI_BLOCKS, 256>>>(cpar, cpar1, b1p, h1, nullptr);
    // 4) BN2 stats + transpose W2 + bias
    k_colstat_part_h<<<dim3(2, 16), 256>>>(h1, ps2, pq2, HID, HID, 1.0f);
    k_colstat_final<<<2, 256>>>(ps2, pq2, bn2_g, bn2_b, sc2, t2, HID);
    k_transpose_split<<<dim3(HID / 32, HID / 32), dim3(32, 8)>>>(W2, sc2, t2, HID, HID,
                                                                 1.0f, w2t, bp2);
    k_bias_final<<<1, 512>>>(b2, bp2, b2p, HID / 32);
    // 5) h2 = relu(h1 @ W2p + b2p): split-K x2 fp16 MMA + epilogue (fp32 out)
    k_mma<<<dim3(4, 32, 2), 256, SMEM_MMA_BYTES>>>(h1, w2t, cpar, HID, (HID / BK) / 2);
    k_epi<<<EPI_BLOCKS, 256>>>(cpar, cpar1, b2p, nullptr, h2);
    // 6) BN3 stats + collapsed GEMM3 coefficients
    k_colstat_part<<<dim3(2, 16), 256>>>(h2, ps3, pq3, HID);
    k_colstat_final<<<2, 256>>>(ps3, pq3, bn3_g, bn3_b, sc3, t3, HID);
    k_coeff<<<HID, 128>>>(W3, sc3, t3, coeff, cpart);
    // 7) scores
    k_scores<<<BATCH / 8, 256>>>(h2, lr, coeff, cpart, b3, bias, out);
}